// round 1
// baseline (speedup 1.0000x reference)
#include <cuda_runtime.h>

#define D 64
#define NMAX 50048
#define EMAX 800000

// ---------------- scratch (no allocation allowed) ----------------
__device__ int   g_degi[NMAX];
__device__ int   g_cursor[NMAX];
__device__ float g_dinv[NMAX];
__device__ int   g_rowptr[NMAX + 1];
__device__ int   g_scan_tmp[NMAX];
__device__ int   g_bsum[64];
__device__ int   g_boff[64];
__device__ int   g_esrc[EMAX];
__device__ float g_ewn[EMAX];
__device__ float g_hA[(size_t)NMAX * D];
__device__ float g_hB[(size_t)NMAX * D];
__device__ float g_acc[(size_t)NMAX * D];
__device__ float g_y[(size_t)NMAX * D];

// ---------------- CSR build ----------------
__global__ void k_deg(const int* __restrict__ dst, int E) {
    int e = blockIdx.x * blockDim.x + threadIdx.x;
    if (e < E) atomicAdd(&g_degi[dst[e]], 1);
}

__global__ void k_scan1(int n) {
    __shared__ int sm[1024];
    int i = blockIdx.x * 1024 + threadIdx.x;
    int v = (i < n) ? g_degi[i] : 0;
    sm[threadIdx.x] = v;
    __syncthreads();
    for (int off = 1; off < 1024; off <<= 1) {
        int t = (threadIdx.x >= off) ? sm[threadIdx.x - off] : 0;
        __syncthreads();
        sm[threadIdx.x] += t;
        __syncthreads();
    }
    if (i < n) g_scan_tmp[i] = sm[threadIdx.x];
    if (threadIdx.x == 1023) g_bsum[blockIdx.x] = sm[1023];
}

__global__ void k_scan2(int nb) {
    __shared__ int sm[64];
    int t = threadIdx.x;
    int v = (t < nb) ? g_bsum[t] : 0;
    sm[t] = v;
    __syncthreads();
    for (int off = 1; off < 64; off <<= 1) {
        int u = (t >= off) ? sm[t - off] : 0;
        __syncthreads();
        sm[t] += u;
        __syncthreads();
    }
    g_boff[t] = sm[t] - v;  // exclusive prefix of block sums
}

__global__ void k_scan3(int n) {
    int i = blockIdx.x * blockDim.x + threadIdx.x;
    if (i < n) {
        int incl = g_scan_tmp[i] + g_boff[i >> 10];
        g_rowptr[i] = incl - g_degi[i];
        if (i == n - 1) g_rowptr[n] = incl;
    }
}

__global__ void k_dinv(int n) {
    int i = blockIdx.x * blockDim.x + threadIdx.x;
    if (i < n) {
        int d = g_degi[i];
        g_dinv[i] = (d > 0) ? rsqrtf((float)d) : 0.0f;
    }
}

__global__ void k_fill(const int* __restrict__ src, const int* __restrict__ dst, int E) {
    int e = blockIdx.x * blockDim.x + threadIdx.x;
    if (e >= E) return;
    int s = src[e], d = dst[e];
    int pos = g_rowptr[d] + atomicAdd(&g_cursor[d], 1);
    g_esrc[pos] = s;
    g_ewn[pos] = g_dinv[s] * g_dinv[d];
}

// ---------------- propagation: warp per node, gather-only ----------------
__global__ void __launch_bounds__(256) k_hop(const float* __restrict__ hin,
                                             float* __restrict__ hout, int N) {
    int node = (blockIdx.x * blockDim.x + threadIdx.x) >> 5;
    int lane = threadIdx.x & 31;
    if (node >= N) return;
    int p = g_rowptr[node];
    int end = g_rowptr[node + 1];
    float ax = 0.0f, ay = 0.0f;
    for (; p + 2 <= end; p += 2) {
        int s0 = g_esrc[p];
        int s1 = g_esrc[p + 1];
        float w0 = g_ewn[p];
        float w1 = g_ewn[p + 1];
        float2 v0 = *(const float2*)&hin[(size_t)s0 * D + lane * 2];
        float2 v1 = *(const float2*)&hin[(size_t)s1 * D + lane * 2];
        ax += w0 * v0.x;  ay += w0 * v0.y;
        ax += w1 * v1.x;  ay += w1 * v1.y;
    }
    if (p < end) {
        int s0 = g_esrc[p];
        float w0 = g_ewn[p];
        float2 v0 = *(const float2*)&hin[(size_t)s0 * D + lane * 2];
        ax += w0 * v0.x;  ay += w0 * v0.y;
    }
    float2 r;  r.x = ax;  r.y = ay;
    *(float2*)&hout[(size_t)node * D + lane * 2] = r;
}

// ---------------- GEMM: [N,64] @ [64,64], fused bias/acc/prelu ----------------
// MODE 0: acc = H@W + b     MODE 1: acc += H@W     MODE 2: Y = prelu(acc + H@W)
template <int MODE>
__global__ void __launch_bounds__(256) k_gemm(const float* __restrict__ H,
                                              const float* __restrict__ W,
                                              float* __restrict__ acc,
                                              const float* __restrict__ bias,
                                              const float* __restrict__ alpha,
                                              float* __restrict__ Y, int N) {
    __shared__ float Hs[64][68];
    __shared__ float Ws[64][64];
    const int tid = threadIdx.x;
    const int n0 = blockIdx.x * 64;

    {   // stage W tile (64x64)
        const float4* Wv = (const float4*)W;
        float4* Wsv = (float4*)Ws;
#pragma unroll
        for (int i = 0; i < 4; i++) Wsv[tid + i * 256] = Wv[tid + i * 256];
    }
#pragma unroll
    for (int i = 0; i < 4; i++) {  // stage H tile (64 rows)
        int idx = tid + i * 256;
        int r = idx >> 4;
        int c4 = (idx & 15) << 2;
        float4 v = make_float4(0.f, 0.f, 0.f, 0.f);
        if (n0 + r < N) v = *(const float4*)&H[(size_t)(n0 + r) * 64 + c4];
        Hs[r][c4 + 0] = v.x; Hs[r][c4 + 1] = v.y;
        Hs[r][c4 + 2] = v.z; Hs[r][c4 + 3] = v.w;
    }
    __syncthreads();

    const int r0 = (tid >> 4) * 4;
    const int c0 = (tid & 15) * 4;
    unsigned long long c01[4] = {0ull, 0ull, 0ull, 0ull};
    unsigned long long c23[4] = {0ull, 0ull, 0ull, 0ull};

#pragma unroll 4
    for (int k = 0; k < 64; k++) {
        ulonglong2 w = *(const ulonglong2*)&Ws[k][c0];   // cols c0..c0+3 as 2x f32x2
#pragma unroll
        for (int i = 0; i < 4; i++) {
            float a = Hs[r0 + i][k];
            unsigned long long aa;
            asm("mov.b64 %0, {%1, %1};" : "=l"(aa) : "f"(a));
            asm("fma.rn.f32x2 %0, %1, %2, %0;" : "+l"(c01[i]) : "l"(aa), "l"(w.x));
            asm("fma.rn.f32x2 %0, %1, %2, %0;" : "+l"(c23[i]) : "l"(aa), "l"(w.y));
        }
    }

    float a0 = 0.0f;
    if (MODE == 2) a0 = alpha[0];
    float4 bv = make_float4(0.f, 0.f, 0.f, 0.f);
    if (MODE == 0) bv = *(const float4*)&bias[c0];

#pragma unroll
    for (int i = 0; i < 4; i++) {
        int row = n0 + r0 + i;
        if (row < N) {
            float x0, x1, x2, x3;
            asm("mov.b64 {%0, %1}, %2;" : "=f"(x0), "=f"(x1) : "l"(c01[i]));
            asm("mov.b64 {%0, %1}, %2;" : "=f"(x2), "=f"(x3) : "l"(c23[i]));
            float* ap = &acc[(size_t)row * 64 + c0];
            if (MODE == 0) {
                float4 o;
                o.x = x0 + bv.x; o.y = x1 + bv.y; o.z = x2 + bv.z; o.w = x3 + bv.w;
                *(float4*)ap = o;
            } else if (MODE == 1) {
                float4 o = *(const float4*)ap;
                o.x += x0; o.y += x1; o.z += x2; o.w += x3;
                *(float4*)ap = o;
            } else {
                float4 o = *(const float4*)ap;
                o.x += x0; o.y += x1; o.z += x2; o.w += x3;
                o.x = (o.x >= 0.f) ? o.x : a0 * o.x;
                o.y = (o.y >= 0.f) ? o.y : a0 * o.y;
                o.z = (o.z >= 0.f) ? o.z : a0 * o.z;
                o.w = (o.w >= 0.f) ? o.w : a0 * o.w;
                *(float4*)&Y[(size_t)row * 64 + c0] = o;
            }
        }
    }
}

// ---------------- fused pool + critic head ----------------
__global__ void k_out_init(float* __restrict__ out, const float* __restrict__ bout, int G) {
    int i = threadIdx.x;
    if (i < G) out[i] = bout[0];
}

__global__ void __launch_bounds__(256) k_pool(const float* __restrict__ h,
                                              const int* __restrict__ bids,
                                              const float* __restrict__ Wout,
                                              float* __restrict__ out, int N) {
    int node = (blockIdx.x * blockDim.x + threadIdx.x) >> 5;
    int lane = threadIdx.x & 31;
    if (node >= N) return;
    float2 hv = *(const float2*)&h[(size_t)node * D + lane * 2];
    float2 wv = *(const float2*)&Wout[lane * 2];
    float s = hv.x * wv.x + hv.y * wv.y;
#pragma unroll
    for (int off = 16; off; off >>= 1) s += __shfl_xor_sync(0xffffffffu, s, off);
    if (lane == 0) atomicAdd(&out[bids[node]], s);
}

// ---------------- launch ----------------
extern "C" void kernel_launch(void* const* d_in, const int* in_sizes, int n_in,
                              void* d_out, int out_size) {
    const float* x    = (const float*)d_in[0];
    const int*   ei   = (const int*)d_in[1];
    const int*   bids = (const int*)d_in[2];
    const float* W0   = (const float*)d_in[3];
    const float* b0   = (const float*)d_in[4];
    const float* W1   = (const float*)d_in[5];
    const float* b1   = (const float*)d_in[6];
    const float* al0  = (const float*)d_in[7];
    const float* al1  = (const float*)d_in[8];
    const float* Wout = (const float*)d_in[9];
    const float* bout = (const float*)d_in[10];
    float* out = (float*)d_out;

    const int N = in_sizes[0] / D;
    const int E = in_sizes[1] / 2;
    const int* src = ei;
    const int* dst = ei + E;

    void *p_degi, *p_cursor;
    float *hA, *hB, *accp, *yp;
    cudaGetSymbolAddress(&p_degi, g_degi);
    cudaGetSymbolAddress(&p_cursor, g_cursor);
    cudaGetSymbolAddress((void**)&hA, g_hA);
    cudaGetSymbolAddress((void**)&hB, g_hB);
    cudaGetSymbolAddress((void**)&accp, g_acc);
    cudaGetSymbolAddress((void**)&yp, g_y);

    cudaMemsetAsync(p_degi, 0, (size_t)N * sizeof(int));
    cudaMemsetAsync(p_cursor, 0, (size_t)N * sizeof(int));

    const int eb = (E + 255) / 256;
    const int nb1024 = (N + 1023) / 1024;
    k_deg<<<eb, 256>>>(dst, E);
    k_scan1<<<nb1024, 1024>>>(N);
    k_scan2<<<1, 64>>>(nb1024);
    k_scan3<<<(N + 255) / 256, 256>>>(N);
    k_dinv<<<(N + 255) / 256, 256>>>(N);
    k_fill<<<eb, 256>>>(src, dst, E);

    const int gb = (N + 63) / 64;
    const int hb = (N * 32 + 255) / 256;

    // ---- layer 0 ----
    k_gemm<0><<<gb, 256>>>(x,  W0,          accp, b0, nullptr, nullptr, N);
    k_hop<<<hb, 256>>>(x, hB, N);
    k_gemm<1><<<gb, 256>>>(hB, W0 + 4096,   accp, nullptr, nullptr, nullptr, N);
    k_hop<<<hb, 256>>>(hB, hA, N);
    k_gemm<1><<<gb, 256>>>(hA, W0 + 8192,   accp, nullptr, nullptr, nullptr, N);
    k_hop<<<hb, 256>>>(hA, hB, N);
    k_gemm<2><<<gb, 256>>>(hB, W0 + 12288,  accp, nullptr, al0, yp, N);

    // ---- layer 1 ----
    k_gemm<0><<<gb, 256>>>(yp, W1,          accp, b1, nullptr, nullptr, N);
    k_hop<<<hb, 256>>>(yp, hB, N);
    k_gemm<1><<<gb, 256>>>(hB, W1 + 4096,   accp, nullptr, nullptr, nullptr, N);
    k_hop<<<hb, 256>>>(hB, hA, N);
    k_gemm<1><<<gb, 256>>>(hA, W1 + 8192,   accp, nullptr, nullptr, nullptr, N);
    k_hop<<<hb, 256>>>(hA, hB, N);
    k_gemm<2><<<gb, 256>>>(hB, W1 + 12288,  accp, nullptr, al1, yp, N);

    // ---- pool + head ----
    k_out_init<<<1, 128>>>(out, bout, out_size);
    k_pool<<<hb, 256>>>(yp, bids, Wout, out, N);
}

// round 2
// speedup vs baseline: 1.0468x; 1.0468x over previous
#include <cuda_runtime.h>
#include <cuda_fp16.h>

#define D 64
#define NMAX 50048
#define EMAX 800000

// ---------------- scratch (no allocation allowed) ----------------
__device__ int    g_degi[NMAX];
__device__ int    g_cursor[NMAX];
__device__ float  g_dinv[NMAX];
__device__ int    g_rowptr[NMAX + 1];
__device__ int    g_scan_tmp[NMAX];
__device__ int    g_bsum[64];
__device__ int    g_boff[64];
__device__ int2   g_edge[EMAX];          // {src, wn as float bits}
__device__ __half g_x16[(size_t)NMAX * D];
__device__ __half g_hA16[(size_t)NMAX * D];
__device__ __half g_hB16[(size_t)NMAX * D];
__device__ __half g_y16[(size_t)NMAX * D];
__device__ float  g_acc[(size_t)NMAX * D];

// ---------------- CSR build ----------------
__global__ void k_deg(const int* __restrict__ dst, int E) {
    int e = blockIdx.x * blockDim.x + threadIdx.x;
    if (e < E) atomicAdd(&g_degi[dst[e]], 1);
}

__global__ void k_scan1(int n) {
    __shared__ int sm[1024];
    int i = blockIdx.x * 1024 + threadIdx.x;
    int v = (i < n) ? g_degi[i] : 0;
    sm[threadIdx.x] = v;
    __syncthreads();
    for (int off = 1; off < 1024; off <<= 1) {
        int t = (threadIdx.x >= off) ? sm[threadIdx.x - off] : 0;
        __syncthreads();
        sm[threadIdx.x] += t;
        __syncthreads();
    }
    if (i < n) g_scan_tmp[i] = sm[threadIdx.x];
    if (threadIdx.x == 1023) g_bsum[blockIdx.x] = sm[1023];
}

__global__ void k_scan2(int nb) {
    __shared__ int sm[64];
    int t = threadIdx.x;
    int v = (t < nb) ? g_bsum[t] : 0;
    sm[t] = v;
    __syncthreads();
    for (int off = 1; off < 64; off <<= 1) {
        int u = (t >= off) ? sm[t - off] : 0;
        __syncthreads();
        sm[t] += u;
        __syncthreads();
    }
    g_boff[t] = sm[t] - v;
}

// scan finish + dinv + cursor init (fused)
__global__ void k_scan3(int n) {
    int i = blockIdx.x * blockDim.x + threadIdx.x;
    if (i < n) {
        int di = g_degi[i];
        int incl = g_scan_tmp[i] + g_boff[i >> 10];
        int excl = incl - di;
        g_rowptr[i] = excl;
        g_cursor[i] = excl;
        g_dinv[i] = (di > 0) ? rsqrtf((float)di) : 0.0f;
        if (i == n - 1) g_rowptr[n] = incl;
    }
}

__global__ void k_fill(const int* __restrict__ src, const int* __restrict__ dst, int E) {
    int e = blockIdx.x * blockDim.x + threadIdx.x;
    if (e >= E) return;
    int s = src[e], d = dst[e];
    int pos = atomicAdd(&g_cursor[d], 1);
    int2 ed;
    ed.x = s;
    ed.y = __float_as_int(g_dinv[s] * g_dinv[d]);
    g_edge[pos] = ed;
}

// ---------------- quantize x to fp16 ----------------
__global__ void k_quant(const float* __restrict__ x, __half* __restrict__ o, int n4) {
    int i = blockIdx.x * blockDim.x + threadIdx.x;
    if (i >= n4) return;
    float4 v = ((const float4*)x)[i];
    __half2 a = __floats2half2_rn(v.x, v.y);
    __half2 b = __floats2half2_rn(v.z, v.w);
    uint2 p;
    p.x = *(unsigned*)&a;
    p.y = *(unsigned*)&b;
    ((uint2*)o)[i] = p;
}

// ---------------- fused stage: (optional hop) + GEMM + epilogue ----------------
// MODE 0: Hs <- global hin;     acc = Hs@W + bias
// MODE 1: Hs <- hop(hin);       acc += Hs@W;  hout <- hop result (fp16)
// MODE 2: Hs <- hop(hin);       hout <- prelu(acc + Hs@W) (fp16)
template <int MODE>
__global__ void __launch_bounds__(256) k_stage(const __half* __restrict__ hin,
                                               const float* __restrict__ W,
                                               float* __restrict__ acc,
                                               const float* __restrict__ bias,
                                               const float* __restrict__ alpha,
                                               __half* __restrict__ hout, int N) {
    __shared__ float Hs[64][65];
    __shared__ float Ws[64][64];
    const int tid = threadIdx.x;
    const int n0 = blockIdx.x * 64;

    {   // stage W tile (64x64 fp32)
        const float4* Wv = (const float4*)W;
        float4* Wsv = (float4*)Ws;
#pragma unroll
        for (int i = 0; i < 4; i++) Wsv[tid + i * 256] = Wv[tid + i * 256];
    }

    if (MODE == 0) {
        // load H tile directly from fp16 global
#pragma unroll
        for (int i = 0; i < 4; i++) {
            int idx = tid + i * 256;
            int r = idx >> 4;
            int c = (idx & 15) << 2;
            float2 a = make_float2(0.f, 0.f), b = make_float2(0.f, 0.f);
            if (n0 + r < N) {
                const __half2* hp = (const __half2*)&hin[(size_t)(n0 + r) * D + c];
                a = __half22float2(hp[0]);
                b = __half22float2(hp[1]);
            }
            Hs[r][c + 0] = a.x; Hs[r][c + 1] = a.y;
            Hs[r][c + 2] = b.x; Hs[r][c + 3] = b.y;
        }
    } else {
        // hop for this block's 64 nodes: warp per node, 8 nodes per warp
        const int w = tid >> 5, lane = tid & 31;
#pragma unroll
        for (int i = 0; i < 8; i++) {
            int r = i * 8 + w;
            int node = n0 + r;
            float ax = 0.f, ay = 0.f;
            if (node < N) {
                int p = g_rowptr[node];
                int end = g_rowptr[node + 1];
                for (; p + 2 <= end; p += 2) {
                    int2 e0 = g_edge[p];
                    int2 e1 = g_edge[p + 1];
                    float w0 = __int_as_float(e0.y);
                    float w1 = __int_as_float(e1.y);
                    float2 v0 = __half22float2(*(const __half2*)&hin[(size_t)e0.x * D + lane * 2]);
                    float2 v1 = __half22float2(*(const __half2*)&hin[(size_t)e1.x * D + lane * 2]);
                    ax += w0 * v0.x; ay += w0 * v0.y;
                    ax += w1 * v1.x; ay += w1 * v1.y;
                }
                if (p < end) {
                    int2 e0 = g_edge[p];
                    float w0 = __int_as_float(e0.y);
                    float2 v0 = __half22float2(*(const __half2*)&hin[(size_t)e0.x * D + lane * 2]);
                    ax += w0 * v0.x; ay += w0 * v0.y;
                }
            }
            Hs[r][lane * 2] = ax;
            Hs[r][lane * 2 + 1] = ay;
            if (MODE == 1 && node < N)
                *(__half2*)&hout[(size_t)node * D + lane * 2] = __floats2half2_rn(ax, ay);
        }
    }
    __syncthreads();

    // 4x4 microtile GEMM with packed f32x2 FMA
    const int r0 = (tid >> 4) * 4;
    const int c0 = (tid & 15) * 4;
    unsigned long long c01[4] = {0ull, 0ull, 0ull, 0ull};
    unsigned long long c23[4] = {0ull, 0ull, 0ull, 0ull};

#pragma unroll 4
    for (int k = 0; k < 64; k++) {
        ulonglong2 wv = *(const ulonglong2*)&Ws[k][c0];
#pragma unroll
        for (int i = 0; i < 4; i++) {
            float a = Hs[r0 + i][k];
            unsigned long long aa;
            asm("mov.b64 %0, {%1, %1};" : "=l"(aa) : "f"(a));
            asm("fma.rn.f32x2 %0, %1, %2, %0;" : "+l"(c01[i]) : "l"(aa), "l"(wv.x));
            asm("fma.rn.f32x2 %0, %1, %2, %0;" : "+l"(c23[i]) : "l"(aa), "l"(wv.y));
        }
    }

    float a0 = 0.0f;
    if (MODE == 2) a0 = alpha[0];
    float4 bv = make_float4(0.f, 0.f, 0.f, 0.f);
    if (MODE == 0) bv = *(const float4*)&bias[c0];

#pragma unroll
    for (int i = 0; i < 4; i++) {
        int row = n0 + r0 + i;
        if (row < N) {
            float x0, x1, x2, x3;
            asm("mov.b64 {%0, %1}, %2;" : "=f"(x0), "=f"(x1) : "l"(c01[i]));
            asm("mov.b64 {%0, %1}, %2;" : "=f"(x2), "=f"(x3) : "l"(c23[i]));
            float* ap = &acc[(size_t)row * D + c0];
            if (MODE == 0) {
                float4 o;
                o.x = x0 + bv.x; o.y = x1 + bv.y; o.z = x2 + bv.z; o.w = x3 + bv.w;
                *(float4*)ap = o;
            } else if (MODE == 1) {
                float4 o = *(const float4*)ap;
                o.x += x0; o.y += x1; o.z += x2; o.w += x3;
                *(float4*)ap = o;
            } else {
                float4 o = *(const float4*)ap;
                o.x += x0; o.y += x1; o.z += x2; o.w += x3;
                o.x = (o.x >= 0.f) ? o.x : a0 * o.x;
                o.y = (o.y >= 0.f) ? o.y : a0 * o.y;
                o.z = (o.z >= 0.f) ? o.z : a0 * o.z;
                o.w = (o.w >= 0.f) ? o.w : a0 * o.w;
                __half2 h01 = __floats2half2_rn(o.x, o.y);
                __half2 h23 = __floats2half2_rn(o.z, o.w);
                uint2 pk;
                pk.x = *(unsigned*)&h01;
                pk.y = *(unsigned*)&h23;
                *(uint2*)&hout[(size_t)row * D + c0] = pk;
            }
        }
    }
}

// ---------------- fused pool + critic head ----------------
__global__ void k_out_init(float* __restrict__ out, const float* __restrict__ bout, int G) {
    int i = threadIdx.x;
    if (i < G) out[i] = bout[0];
}

__global__ void __launch_bounds__(256) k_pool(const __half* __restrict__ h,
                                              const int* __restrict__ bids,
                                              const float* __restrict__ Wout,
                                              float* __restrict__ out, int N) {
    int node = (blockIdx.x * blockDim.x + threadIdx.x) >> 5;
    int lane = threadIdx.x & 31;
    if (node >= N) return;
    float2 hv = __half22float2(*(const __half2*)&h[(size_t)node * D + lane * 2]);
    float2 wv = *(const float2*)&Wout[lane * 2];
    float s = hv.x * wv.x + hv.y * wv.y;
#pragma unroll
    for (int off = 16; off; off >>= 1) s += __shfl_xor_sync(0xffffffffu, s, off);
    if (lane == 0) atomicAdd(&out[bids[node]], s);
}

// ---------------- launch ----------------
extern "C" void kernel_launch(void* const* d_in, const int* in_sizes, int n_in,
                              void* d_out, int out_size) {
    const float* x    = (const float*)d_in[0];
    const int*   ei   = (const int*)d_in[1];
    const int*   bids = (const int*)d_in[2];
    const float* W0   = (const float*)d_in[3];
    const float* b0   = (const float*)d_in[4];
    const float* W1   = (const float*)d_in[5];
    const float* b1   = (const float*)d_in[6];
    const float* al0  = (const float*)d_in[7];
    const float* al1  = (const float*)d_in[8];
    const float* Wout = (const float*)d_in[9];
    const float* bout = (const float*)d_in[10];
    float* out = (float*)d_out;

    const int N = in_sizes[0] / D;
    const int E = in_sizes[1] / 2;
    const int* src = ei;
    const int* dst = ei + E;

    void* p_degi;
    __half *x16, *hA, *hB, *y16;
    float* accp;
    cudaGetSymbolAddress(&p_degi, g_degi);
    cudaGetSymbolAddress((void**)&x16, g_x16);
    cudaGetSymbolAddress((void**)&hA, g_hA16);
    cudaGetSymbolAddress((void**)&hB, g_hB16);
    cudaGetSymbolAddress((void**)&y16, g_y16);
    cudaGetSymbolAddress((void**)&accp, g_acc);

    cudaMemsetAsync(p_degi, 0, (size_t)N * sizeof(int));

    const int eb = (E + 255) / 256;
    const int nb1024 = (N + 1023) / 1024;
    k_deg<<<eb, 256>>>(dst, E);
    k_scan1<<<nb1024, 1024>>>(N);
    k_scan2<<<1, 64>>>(nb1024);
    k_scan3<<<(N + 255) / 256, 256>>>(N);
    k_fill<<<eb, 256>>>(src, dst, E);
    k_quant<<<(N * 16 + 255) / 256, 256>>>(x, x16, N * 16);

    const int gb = (N + 63) / 64;

    // ---- layer 0 ----
    k_stage<0><<<gb, 256>>>(x16, W0,          accp, b0, nullptr, nullptr, N);
    k_stage<1><<<gb, 256>>>(x16, W0 + 4096,   accp, nullptr, nullptr, hA, N);
    k_stage<1><<<gb, 256>>>(hA,  W0 + 8192,   accp, nullptr, nullptr, hB, N);
    k_stage<2><<<gb, 256>>>(hB,  W0 + 12288,  accp, nullptr, al0, y16, N);

    // ---- layer 1 ----
    k_stage<0><<<gb, 256>>>(y16, W1,          accp, b1, nullptr, nullptr, N);
    k_stage<1><<<gb, 256>>>(y16, W1 + 4096,   accp, nullptr, nullptr, hA, N);
    k_stage<1><<<gb, 256>>>(hA,  W1 + 8192,   accp, nullptr, nullptr, hB, N);
    k_stage<2><<<gb, 256>>>(hB,  W1 + 12288,  accp, nullptr, al1, hA, N);

    // ---- pool + head ----
    k_out_init<<<1, 128>>>(out, bout, out_size);
    k_pool<<<(N * 32 + 255) / 256, 256>>>(hA, bids, Wout, out, N);
}

// round 3
// speedup vs baseline: 1.0557x; 1.0085x over previous
#include <cuda_runtime.h>
#include <cuda_fp16.h>

#define D 64
#define NMAX 50048
#define EMAX 800000

// ---------------- scratch (no allocation allowed) ----------------
__device__ int    g_degi[NMAX];
__device__ int    g_cursor[NMAX];
__device__ float  g_dinv[NMAX];
__device__ int    g_rowptr[NMAX + 1];
__device__ int    g_scan_tmp[NMAX];
__device__ int    g_bsum[64];
__device__ int    g_boff[64];
__device__ int2   g_edge[EMAX + 2];      // {src, wn bits}; padded for int4 tail
__device__ __half g_x16[(size_t)NMAX * D];
__device__ __half g_hA16[(size_t)NMAX * D];
__device__ __half g_hB16[(size_t)NMAX * D];
__device__ __half g_y16[(size_t)NMAX * D];
__device__ float  g_acc[(size_t)NMAX * D];

// ---------------- CSR build ----------------
__global__ void k_deg(const int* __restrict__ dst, int E) {
    int e = blockIdx.x * blockDim.x + threadIdx.x;
    if (e < E) atomicAdd(&g_degi[dst[e]], 1);
}

__global__ void k_scan1(int n) {
    __shared__ int sm[1024];
    int i = blockIdx.x * 1024 + threadIdx.x;
    int v = (i < n) ? g_degi[i] : 0;
    sm[threadIdx.x] = v;
    __syncthreads();
    for (int off = 1; off < 1024; off <<= 1) {
        int t = (threadIdx.x >= off) ? sm[threadIdx.x - off] : 0;
        __syncthreads();
        sm[threadIdx.x] += t;
        __syncthreads();
    }
    if (i < n) g_scan_tmp[i] = sm[threadIdx.x];
    if (threadIdx.x == 1023) g_bsum[blockIdx.x] = sm[1023];
}

__global__ void k_scan2(int nb) {
    __shared__ int sm[64];
    int t = threadIdx.x;
    int v = (t < nb) ? g_bsum[t] : 0;
    sm[t] = v;
    __syncthreads();
    for (int off = 1; off < 64; off <<= 1) {
        int u = (t >= off) ? sm[t - off] : 0;
        __syncthreads();
        sm[t] += u;
        __syncthreads();
    }
    g_boff[t] = sm[t] - v;
}

__global__ void k_scan3(int n) {
    int i = blockIdx.x * blockDim.x + threadIdx.x;
    if (i < n) {
        int di = g_degi[i];
        int incl = g_scan_tmp[i] + g_boff[i >> 10];
        int excl = incl - di;
        g_rowptr[i] = excl;
        g_cursor[i] = excl;
        g_dinv[i] = (di > 0) ? rsqrtf((float)di) : 0.0f;
        if (i == n - 1) g_rowptr[n] = incl;
    }
}

__global__ void k_fill(const int* __restrict__ src, const int* __restrict__ dst, int E) {
    int e = blockIdx.x * blockDim.x + threadIdx.x;
    if (e >= E) return;
    int s = src[e], d = dst[e];
    int pos = atomicAdd(&g_cursor[d], 1);
    int2 ed;
    ed.x = s;
    ed.y = __float_as_int(g_dinv[s] * g_dinv[d]);
    g_edge[pos] = ed;
}

// ---------------- quantize x to fp16 ----------------
__global__ void k_quant(const float* __restrict__ x, __half* __restrict__ o, int n4) {
    int i = blockIdx.x * blockDim.x + threadIdx.x;
    if (i >= n4) return;
    float4 v = ((const float4*)x)[i];
    __half2 a = __floats2half2_rn(v.x, v.y);
    __half2 b = __floats2half2_rn(v.z, v.w);
    uint2 p;
    p.x = *(unsigned*)&a;
    p.y = *(unsigned*)&b;
    ((uint2*)o)[i] = p;
}

// ---------------- stage kernel: GEMM blocks + hop blocks in one grid ----
// Blocks [0, GB): GEMM on h (GMODE 0: acc = h@W + bias; 1: acc += h@W;
//                 2: hout16 = prelu(acc + h@W))
// Blocks [GB, ...): hop  h -> hopout (only when HOP=true)
template <int GMODE, bool HOP>
__global__ void __launch_bounds__(256) k_stage(const __half* __restrict__ hin,
                                               const float* __restrict__ W,
                                               float* __restrict__ acc,
                                               const float* __restrict__ bias,
                                               const float* __restrict__ alpha,
                                               __half* __restrict__ hopout,
                                               __half* __restrict__ y16,
                                               int N, int GB) {
    const int tid = threadIdx.x;

    if (HOP && blockIdx.x >= GB) {
        // ---- hop: warp per node, 4-edge unroll ----
        const int lane = tid & 31;
        const int node = (blockIdx.x - GB) * 8 + (tid >> 5);
        if (node >= N) return;
        int p = g_rowptr[node];
        const int end = g_rowptr[node + 1];
        float ax = 0.f, ay = 0.f;
        if (p < end && (p & 1)) {  // align to int4
            int2 e = g_edge[p];
            float w = __int_as_float(e.y);
            float2 v = __half22float2(__ldg((const __half2*)&hin[(size_t)e.x * D + lane * 2]));
            ax += w * v.x;  ay += w * v.y;
            p++;
        }
        for (; p + 4 <= end; p += 4) {
            int4 a = *(const int4*)&g_edge[p];
            int4 b = *(const int4*)&g_edge[p + 2];
            float w0 = __int_as_float(a.y), w1 = __int_as_float(a.w);
            float w2 = __int_as_float(b.y), w3 = __int_as_float(b.w);
            float2 v0 = __half22float2(__ldg((const __half2*)&hin[(size_t)a.x * D + lane * 2]));
            float2 v1 = __half22float2(__ldg((const __half2*)&hin[(size_t)a.z * D + lane * 2]));
            float2 v2 = __half22float2(__ldg((const __half2*)&hin[(size_t)b.x * D + lane * 2]));
            float2 v3 = __half22float2(__ldg((const __half2*)&hin[(size_t)b.z * D + lane * 2]));
            ax += w0 * v0.x;  ay += w0 * v0.y;
            ax += w1 * v1.x;  ay += w1 * v1.y;
            ax += w2 * v2.x;  ay += w2 * v2.y;
            ax += w3 * v3.x;  ay += w3 * v3.y;
        }
        if (p + 2 <= end) {
            int4 a = *(const int4*)&g_edge[p];
            float w0 = __int_as_float(a.y), w1 = __int_as_float(a.w);
            float2 v0 = __half22float2(__ldg((const __half2*)&hin[(size_t)a.x * D + lane * 2]));
            float2 v1 = __half22float2(__ldg((const __half2*)&hin[(size_t)a.z * D + lane * 2]));
            ax += w0 * v0.x;  ay += w0 * v0.y;
            ax += w1 * v1.x;  ay += w1 * v1.y;
            p += 2;
        }
        if (p < end) {
            int2 e = g_edge[p];
            float w = __int_as_float(e.y);
            float2 v = __half22float2(__ldg((const __half2*)&hin[(size_t)e.x * D + lane * 2]));
            ax += w * v.x;  ay += w * v.y;
        }
        *(__half2*)&hopout[(size_t)node * D + lane * 2] = __floats2half2_rn(ax, ay);
        return;
    }

    // ---- GEMM: 64-row tile, 4x4 microtile, packed f32x2 FMA ----
    __shared__ float Hs[64][65];
    __shared__ float Ws[64][64];
    const int n0 = blockIdx.x * 64;

    {
        const float4* Wv = (const float4*)W;
        float4* Wsv = (float4*)Ws;
#pragma unroll
        for (int i = 0; i < 4; i++) Wsv[tid + i * 256] = Wv[tid + i * 256];
    }
#pragma unroll
    for (int i = 0; i < 4; i++) {
        int idx = tid + i * 256;
        int r = idx >> 4;
        int c = (idx & 15) << 2;
        float2 a = make_float2(0.f, 0.f), b = make_float2(0.f, 0.f);
        if (n0 + r < N) {
            const __half2* hp = (const __half2*)&hin[(size_t)(n0 + r) * D + c];
            a = __half22float2(hp[0]);
            b = __half22float2(hp[1]);
        }
        Hs[r][c + 0] = a.x; Hs[r][c + 1] = a.y;
        Hs[r][c + 2] = b.x; Hs[r][c + 3] = b.y;
    }
    __syncthreads();

    const int r0 = (tid >> 4) * 4;
    const int c0 = (tid & 15) * 4;
    unsigned long long c01[4] = {0ull, 0ull, 0ull, 0ull};
    unsigned long long c23[4] = {0ull, 0ull, 0ull, 0ull};

#pragma unroll 4
    for (int k = 0; k < 64; k++) {
        ulonglong2 wv = *(const ulonglong2*)&Ws[k][c0];
#pragma unroll
        for (int i = 0; i < 4; i++) {
            float a = Hs[r0 + i][k];
            unsigned long long aa;
            asm("mov.b64 %0, {%1, %1};" : "=l"(aa) : "f"(a));
            asm("fma.rn.f32x2 %0, %1, %2, %0;" : "+l"(c01[i]) : "l"(aa), "l"(wv.x));
            asm("fma.rn.f32x2 %0, %1, %2, %0;" : "+l"(c23[i]) : "l"(aa), "l"(wv.y));
        }
    }

    float a0 = 0.0f;
    if (GMODE == 2) a0 = alpha[0];
    float4 bv = make_float4(0.f, 0.f, 0.f, 0.f);
    if (GMODE == 0) bv = *(const float4*)&bias[c0];

#pragma unroll
    for (int i = 0; i < 4; i++) {
        int row = n0 + r0 + i;
        if (row < N) {
            float x0, x1, x2, x3;
            asm("mov.b64 {%0, %1}, %2;" : "=f"(x0), "=f"(x1) : "l"(c01[i]));
            asm("mov.b64 {%0, %1}, %2;" : "=f"(x2), "=f"(x3) : "l"(c23[i]));
            float* ap = &acc[(size_t)row * D + c0];
            if (GMODE == 0) {
                float4 o;
                o.x = x0 + bv.x; o.y = x1 + bv.y; o.z = x2 + bv.z; o.w = x3 + bv.w;
                *(float4*)ap = o;
            } else if (GMODE == 1) {
                float4 o = *(const float4*)ap;
                o.x += x0; o.y += x1; o.z += x2; o.w += x3;
                *(float4*)ap = o;
            } else {
                float4 o = *(const float4*)ap;
                o.x += x0; o.y += x1; o.z += x2; o.w += x3;
                o.x = (o.x >= 0.f) ? o.x : a0 * o.x;
                o.y = (o.y >= 0.f) ? o.y : a0 * o.y;
                o.z = (o.z >= 0.f) ? o.z : a0 * o.z;
                o.w = (o.w >= 0.f) ? o.w : a0 * o.w;
                __half2 h01 = __floats2half2_rn(o.x, o.y);
                __half2 h23 = __floats2half2_rn(o.z, o.w);
                uint2 pk;
                pk.x = *(unsigned*)&h01;
                pk.y = *(unsigned*)&h23;
                *(uint2*)&y16[(size_t)row * D + c0] = pk;
            }
        }
    }
}

// ---------------- fused pool + critic head ----------------
__global__ void k_out_init(float* __restrict__ out, const float* __restrict__ bout, int G) {
    int i = threadIdx.x;
    if (i < G) out[i] = bout[0];
}

__global__ void __launch_bounds__(256) k_pool(const __half* __restrict__ h,
                                              const int* __restrict__ bids,
                                              const float* __restrict__ Wout,
                                              float* __restrict__ out, int N) {
    int node = (blockIdx.x * blockDim.x + threadIdx.x) >> 5;
    int lane = threadIdx.x & 31;
    if (node >= N) return;
    float2 hv = __half22float2(*(const __half2*)&h[(size_t)node * D + lane * 2]);
    float2 wv = *(const float2*)&Wout[lane * 2];
    float s = hv.x * wv.x + hv.y * wv.y;
#pragma unroll
    for (int off = 16; off; off >>= 1) s += __shfl_xor_sync(0xffffffffu, s, off);
    if (lane == 0) atomicAdd(&out[bids[node]], s);
}

// ---------------- launch ----------------
extern "C" void kernel_launch(void* const* d_in, const int* in_sizes, int n_in,
                              void* d_out, int out_size) {
    const float* x    = (const float*)d_in[0];
    const int*   ei   = (const int*)d_in[1];
    const int*   bids = (const int*)d_in[2];
    const float* W0   = (const float*)d_in[3];
    const float* b0   = (const float*)d_in[4];
    const float* W1   = (const float*)d_in[5];
    const float* b1   = (const float*)d_in[6];
    const float* al0  = (const float*)d_in[7];
    const float* al1  = (const float*)d_in[8];
    const float* Wout = (const float*)d_in[9];
    const float* bout = (const float*)d_in[10];
    float* out = (float*)d_out;

    const int N = in_sizes[0] / D;
    const int E = in_sizes[1] / 2;
    const int* src = ei;
    const int* dst = ei + E;

    void* p_degi;
    __half *x16, *hA, *hB, *y16;
    float* accp;
    cudaGetSymbolAddress(&p_degi, g_degi);
    cudaGetSymbolAddress((void**)&x16, g_x16);
    cudaGetSymbolAddress((void**)&hA, g_hA16);
    cudaGetSymbolAddress((void**)&hB, g_hB16);
    cudaGetSymbolAddress((void**)&y16, g_y16);
    cudaGetSymbolAddress((void**)&accp, g_acc);

    cudaMemsetAsync(p_degi, 0, (size_t)N * sizeof(int));

    const int eb = (E + 255) / 256;
    const int nb1024 = (N + 1023) / 1024;
    k_deg<<<eb, 256>>>(dst, E);
    k_scan1<<<nb1024, 1024>>>(N);
    k_scan2<<<1, 64>>>(nb1024);
    k_scan3<<<(N + 255) / 256, 256>>>(N);
    k_fill<<<eb, 256>>>(src, dst, E);
    k_quant<<<(N * 16 + 255) / 256, 256>>>(x, x16, N * 16);

    const int GB = (N + 63) / 64;          // gemm blocks
    const int HB = (N + 7) / 8;            // hop blocks (warp per node)
    const int FULL = GB + HB;

    // ---- layer 0 ----
    k_stage<0, true ><<<FULL, 256>>>(x16, W0,         accp, b0, nullptr, hA, nullptr, N, GB);
    k_stage<1, true ><<<FULL, 256>>>(hA,  W0 + 4096,  accp, nullptr, nullptr, hB, nullptr, N, GB);
    k_stage<1, true ><<<FULL, 256>>>(hB,  W0 + 8192,  accp, nullptr, nullptr, hA, nullptr, N, GB);
    k_stage<2, false><<<GB,   256>>>(hA,  W0 + 12288, accp, nullptr, al0, nullptr, y16, N, GB);

    // ---- layer 1 ----
    k_stage<0, true ><<<FULL, 256>>>(y16, W1,         accp, b1, nullptr, hB, nullptr, N, GB);
    k_stage<1, true ><<<FULL, 256>>>(hB,  W1 + 4096,  accp, nullptr, nullptr, hA, nullptr, N, GB);
    k_stage<1, true ><<<FULL, 256>>>(hA,  W1 + 8192,  accp, nullptr, nullptr, hB, nullptr, N, GB);
    k_stage<2, false><<<GB,   256>>>(hB,  W1 + 12288, accp, nullptr, al1, nullptr, y16, N, GB);

    // ---- pool + head ----
    k_out_init<<<1, 128>>>(out, bout, out_size);
    k_pool<<<(N * 32 + 255) / 256, 256>>>(y16, bids, Wout, out, N);
}

// round 4
// speedup vs baseline: 1.1152x; 1.0563x over previous
#include <cuda_runtime.h>
#include <cuda_fp16.h>

#define D 64
#define NMAX 50048
#define EMAX 800000

typedef unsigned long long ull;

// ---------------- scratch (no allocation allowed) ----------------
__device__ int    g_degi[NMAX];
__device__ int    g_cursor[NMAX];
__device__ float  g_dinv[NMAX];
__device__ int    g_rowptr[NMAX + 1];
__device__ ull    g_state[64];           // lookback scan state (value<<2 | status)
__device__ int2   g_edge[EMAX + 4];      // {src, wn bits}; padded for int4 tail
__device__ __half g_x16[(size_t)NMAX * D];
__device__ __half g_hA16[(size_t)NMAX * D];
__device__ __half g_hB16[(size_t)NMAX * D];
__device__ __half g_y16[(size_t)NMAX * D];
__device__ float  g_acc[(size_t)NMAX * D];

// ---------------- degree count (also resets scan state) ----------------
__global__ void k_deg(const int* __restrict__ dst, int E) {
    int e = blockIdx.x * blockDim.x + threadIdx.x;
    if (blockIdx.x == 0 && threadIdx.x < 64) g_state[threadIdx.x] = 0ull;
    if (e < E) atomicAdd(&g_degi[dst[e]], 1);
}

// ---------------- single-pass decoupled-lookback scan + dinv + cursor ----
__global__ void __launch_bounds__(1024) k_scan(int n) {
    const int tid = threadIdx.x;
    const int lane = tid & 31;
    const int w = tid >> 5;
    const int i = blockIdx.x * 1024 + tid;
    int v = (i < n) ? g_degi[i] : 0;

    // warp inclusive scan
    int s = v;
#pragma unroll
    for (int off = 1; off < 32; off <<= 1) {
        int t = __shfl_up_sync(0xffffffffu, s, off);
        if (lane >= off) s += t;
    }
    __shared__ int wsum[32];
    if (lane == 31) wsum[w] = s;
    __syncthreads();
    if (w == 0) {
        int t = wsum[lane];
#pragma unroll
        for (int off = 1; off < 32; off <<= 1) {
            int u = __shfl_up_sync(0xffffffffu, t, off);
            if (lane >= off) t += u;
        }
        wsum[lane] = t;
    }
    __syncthreads();
    const int incl = s + (w > 0 ? wsum[w - 1] : 0);
    const int total = wsum[31];

    __shared__ int base_sh;
    if (tid == 0) {
        if (blockIdx.x == 0) {
            atomicExch(&g_state[0], ((ull)(unsigned)total << 2) | 2ull);
            base_sh = 0;
        } else {
            atomicExch(&g_state[blockIdx.x], ((ull)(unsigned)total << 2) | 1ull);
            int base = 0;
            for (int b = blockIdx.x - 1; b >= 0; b--) {
                ull st;
                do { st = atomicAdd(&g_state[b], 0ull); } while ((st & 3ull) == 0ull);
                base += (int)(unsigned)(st >> 2);
                if ((st & 3ull) == 2ull) break;
            }
            atomicExch(&g_state[blockIdx.x], ((ull)(unsigned)(base + total) << 2) | 2ull);
            base_sh = base;
        }
    }
    __syncthreads();
    const int base = base_sh;

    if (i < n) {
        int di = g_degi[i];
        int inclusive = base + incl;
        int excl = inclusive - di;
        g_rowptr[i] = excl;
        g_cursor[i] = excl;
        g_dinv[i] = (di > 0) ? rsqrtf((float)di) : 0.0f;
        if (i == n - 1) g_rowptr[n] = inclusive;
    }
}

// ---------------- fill CSR + quantize x + init out (block-range split) ----
__global__ void k_fillquant(const int* __restrict__ src, const int* __restrict__ dst,
                            const float* __restrict__ x, __half* __restrict__ x16,
                            const float* __restrict__ bout, float* __restrict__ out,
                            int E, int n4, int G, int EB) {
    if ((int)blockIdx.x < EB) {
        int e = blockIdx.x * 256 + threadIdx.x;
        if (e >= E) return;
        int s = src[e], d = dst[e];
        int pos = atomicAdd(&g_cursor[d], 1);
        int2 ed;
        ed.x = s;
        ed.y = __float_as_int(g_dinv[s] * g_dinv[d]);
        g_edge[pos] = ed;
    } else if ((int)blockIdx.x == gridDim.x - 1) {
        int i = threadIdx.x;
        if (i < G) out[i] = bout[0];
    } else {
        int i = (blockIdx.x - EB) * 256 + threadIdx.x;
        if (i >= n4) return;
        float4 v = ((const float4*)x)[i];
        __half2 a = __floats2half2_rn(v.x, v.y);
        __half2 b = __floats2half2_rn(v.z, v.w);
        uint2 p;
        p.x = *(unsigned*)&a;
        p.y = *(unsigned*)&b;
        ((uint2*)x16)[i] = p;
    }
}

// ---------------- stage kernel: GEMM blocks + hop blocks in one grid ----
// GMODE 0: acc = h@W + bias        GMODE 1: acc += h@W
// GMODE 2: y16 = prelu(acc + h@W)  GMODE 3: pool(prelu(acc + h@W)) -> out atomics
// HOP: blocks [GB,..) compute hopout = Ahat * hin
template <int GMODE, bool HOP>
__global__ void __launch_bounds__(256) k_stage(const __half* __restrict__ hin,
                                               const float* __restrict__ W,
                                               float* __restrict__ acc,
                                               const float* __restrict__ bias,
                                               const float* __restrict__ alpha,
                                               __half* __restrict__ hopout,
                                               __half* __restrict__ y16,
                                               const int* __restrict__ bids,
                                               const float* __restrict__ Wout,
                                               float* __restrict__ out,
                                               int N, int GB) {
    const int tid = threadIdx.x;

    if (HOP && (int)blockIdx.x >= GB) {
        const int lane = tid & 31;
        const int node = (blockIdx.x - GB) * 8 + (tid >> 5);
        if (node >= N) return;
        int p = g_rowptr[node];
        const int end = g_rowptr[node + 1];
        float ax = 0.f, ay = 0.f;
        if (p < end && (p & 1)) {  // align to int4
            int2 e = g_edge[p];
            float wv = __int_as_float(e.y);
            float2 v = __half22float2(__ldg((const __half2*)&hin[(size_t)e.x * D + lane * 2]));
            ax += wv * v.x;  ay += wv * v.y;
            p++;
        }
        for (; p + 8 <= end; p += 8) {  // 8-edge unroll: MLP 8
            int4 a = *(const int4*)&g_edge[p];
            int4 b = *(const int4*)&g_edge[p + 2];
            int4 c = *(const int4*)&g_edge[p + 4];
            int4 dd = *(const int4*)&g_edge[p + 6];
            float2 v0 = __half22float2(__ldg((const __half2*)&hin[(size_t)a.x * D + lane * 2]));
            float2 v1 = __half22float2(__ldg((const __half2*)&hin[(size_t)a.z * D + lane * 2]));
            float2 v2 = __half22float2(__ldg((const __half2*)&hin[(size_t)b.x * D + lane * 2]));
            float2 v3 = __half22float2(__ldg((const __half2*)&hin[(size_t)b.z * D + lane * 2]));
            float2 v4 = __half22float2(__ldg((const __half2*)&hin[(size_t)c.x * D + lane * 2]));
            float2 v5 = __half22float2(__ldg((const __half2*)&hin[(size_t)c.z * D + lane * 2]));
            float2 v6 = __half22float2(__ldg((const __half2*)&hin[(size_t)dd.x * D + lane * 2]));
            float2 v7 = __half22float2(__ldg((const __half2*)&hin[(size_t)dd.z * D + lane * 2]));
            float w0 = __int_as_float(a.y),  w1 = __int_as_float(a.w);
            float w2 = __int_as_float(b.y),  w3 = __int_as_float(b.w);
            float w4 = __int_as_float(c.y),  w5 = __int_as_float(c.w);
            float w6 = __int_as_float(dd.y), w7 = __int_as_float(dd.w);
            ax += w0 * v0.x;  ay += w0 * v0.y;
            ax += w1 * v1.x;  ay += w1 * v1.y;
            ax += w2 * v2.x;  ay += w2 * v2.y;
            ax += w3 * v3.x;  ay += w3 * v3.y;
            ax += w4 * v4.x;  ay += w4 * v4.y;
            ax += w5 * v5.x;  ay += w5 * v5.y;
            ax += w6 * v6.x;  ay += w6 * v6.y;
            ax += w7 * v7.x;  ay += w7 * v7.y;
        }
        for (; p + 2 <= end; p += 2) {
            int4 a = *(const int4*)&g_edge[p];
            float w0 = __int_as_float(a.y), w1 = __int_as_float(a.w);
            float2 v0 = __half22float2(__ldg((const __half2*)&hin[(size_t)a.x * D + lane * 2]));
            float2 v1 = __half22float2(__ldg((const __half2*)&hin[(size_t)a.z * D + lane * 2]));
            ax += w0 * v0.x;  ay += w0 * v0.y;
            ax += w1 * v1.x;  ay += w1 * v1.y;
        }
        if (p < end) {
            int2 e = g_edge[p];
            float wv = __int_as_float(e.y);
            float2 v = __half22float2(__ldg((const __half2*)&hin[(size_t)e.x * D + lane * 2]));
            ax += wv * v.x;  ay += wv * v.y;
        }
        *(__half2*)&hopout[(size_t)node * D + lane * 2] = __floats2half2_rn(ax, ay);
        return;
    }

    // ---- GEMM: 64-row tile, 4x4 microtile, packed f32x2 FMA ----
    __shared__ float Hs[64][65];
    __shared__ float Ws[64][64];
    const int n0 = blockIdx.x * 64;

    {
        const float4* Wv = (const float4*)W;
        float4* Wsv = (float4*)Ws;
#pragma unroll
        for (int i = 0; i < 4; i++) Wsv[tid + i * 256] = Wv[tid + i * 256];
    }
#pragma unroll
    for (int i = 0; i < 4; i++) {
        int idx = tid + i * 256;
        int r = idx >> 4;
        int c = (idx & 15) << 2;
        float2 a = make_float2(0.f, 0.f), b = make_float2(0.f, 0.f);
        if (n0 + r < N) {
            const __half2* hp = (const __half2*)&hin[(size_t)(n0 + r) * D + c];
            a = __half22float2(hp[0]);
            b = __half22float2(hp[1]);
        }
        Hs[r][c + 0] = a.x; Hs[r][c + 1] = a.y;
        Hs[r][c + 2] = b.x; Hs[r][c + 3] = b.y;
    }
    __syncthreads();

    const int r0 = (tid >> 4) * 4;
    const int c0 = (tid & 15) * 4;
    unsigned long long c01[4] = {0ull, 0ull, 0ull, 0ull};
    unsigned long long c23[4] = {0ull, 0ull, 0ull, 0ull};

#pragma unroll 4
    for (int k = 0; k < 64; k++) {
        ulonglong2 wv = *(const ulonglong2*)&Ws[k][c0];
#pragma unroll
        for (int i = 0; i < 4; i++) {
            float a = Hs[r0 + i][k];
            unsigned long long aa;
            asm("mov.b64 %0, {%1, %1};" : "=l"(aa) : "f"(a));
            asm("fma.rn.f32x2 %0, %1, %2, %0;" : "+l"(c01[i]) : "l"(aa), "l"(wv.x));
            asm("fma.rn.f32x2 %0, %1, %2, %0;" : "+l"(c23[i]) : "l"(aa), "l"(wv.y));
        }
    }

    float a0 = 0.0f;
    if (GMODE >= 2) a0 = alpha[0];
    float4 bv = make_float4(0.f, 0.f, 0.f, 0.f);
    if (GMODE == 0) bv = *(const float4*)&bias[c0];
    float4 wov = make_float4(0.f, 0.f, 0.f, 0.f);
    if (GMODE == 3) wov = *(const float4*)&Wout[c0];

#pragma unroll
    for (int i = 0; i < 4; i++) {
        int row = n0 + r0 + i;
        bool valid = (row < N);
        float x0 = 0.f, x1 = 0.f, x2 = 0.f, x3 = 0.f;
        asm("mov.b64 {%0, %1}, %2;" : "=f"(x0), "=f"(x1) : "l"(c01[i]));
        asm("mov.b64 {%0, %1}, %2;" : "=f"(x2), "=f"(x3) : "l"(c23[i]));
        if (GMODE == 0) {
            if (valid) {
                float4 o;
                o.x = x0 + bv.x; o.y = x1 + bv.y; o.z = x2 + bv.z; o.w = x3 + bv.w;
                *(float4*)&acc[(size_t)row * D + c0] = o;
            }
        } else if (GMODE == 1) {
            if (valid) {
                float* ap = &acc[(size_t)row * D + c0];
                float4 o = *(const float4*)ap;
                o.x += x0; o.y += x1; o.z += x2; o.w += x3;
                *(float4*)ap = o;
            }
        } else {
            float4 o = make_float4(0.f, 0.f, 0.f, 0.f);
            if (valid) {
                o = *(const float4*)&acc[(size_t)row * D + c0];
                o.x += x0; o.y += x1; o.z += x2; o.w += x3;
                o.x = (o.x >= 0.f) ? o.x : a0 * o.x;
                o.y = (o.y >= 0.f) ? o.y : a0 * o.y;
                o.z = (o.z >= 0.f) ? o.z : a0 * o.z;
                o.w = (o.w >= 0.f) ? o.w : a0 * o.w;
            }
            if (GMODE == 2) {
                if (valid) {
                    __half2 h01 = __floats2half2_rn(o.x, o.y);
                    __half2 h23 = __floats2half2_rn(o.z, o.w);
                    uint2 pk;
                    pk.x = *(unsigned*)&h01;
                    pk.y = *(unsigned*)&h23;
                    *(uint2*)&y16[(size_t)row * D + c0] = pk;
                }
            } else {  // GMODE 3: fused global_add_pool + critic head
                float part = o.x * wov.x + o.y * wov.y + o.z * wov.z + o.w * wov.w;
#pragma unroll
                for (int off = 8; off; off >>= 1)
                    part += __shfl_xor_sync(0xffffffffu, part, off);
                if ((tid & 15) == 0 && valid)
                    atomicAdd(&out[bids[row]], part);
            }
        }
    }
}

// ---------------- launch ----------------
extern "C" void kernel_launch(void* const* d_in, const int* in_sizes, int n_in,
                              void* d_out, int out_size) {
    const float* x    = (const float*)d_in[0];
    const int*   ei   = (const int*)d_in[1];
    const int*   bids = (const int*)d_in[2];
    const float* W0   = (const float*)d_in[3];
    const float* b0   = (const float*)d_in[4];
    const float* W1   = (const float*)d_in[5];
    const float* b1   = (const float*)d_in[6];
    const float* al0  = (const float*)d_in[7];
    const float* al1  = (const float*)d_in[8];
    const float* Wout = (const float*)d_in[9];
    const float* bout = (const float*)d_in[10];
    float* out = (float*)d_out;

    const int N = in_sizes[0] / D;
    const int E = in_sizes[1] / 2;
    const int* src = ei;
    const int* dst = ei + E;

    void* p_degi;
    __half *x16, *hA, *hB, *y16;
    float* accp;
    cudaGetSymbolAddress(&p_degi, g_degi);
    cudaGetSymbolAddress((void**)&x16, g_x16);
    cudaGetSymbolAddress((void**)&hA, g_hA16);
    cudaGetSymbolAddress((void**)&hB, g_hB16);
    cudaGetSymbolAddress((void**)&y16, g_y16);
    cudaGetSymbolAddress((void**)&accp, g_acc);

    cudaMemsetAsync(p_degi, 0, (size_t)N * sizeof(int));

    const int EB = (E + 255) / 256;
    const int QB = (N * 16 + 255) / 256;
    k_deg<<<EB, 256>>>(dst, E);
    k_scan<<<(N + 1023) / 1024, 1024>>>(N);
    k_fillquant<<<EB + QB + 1, 256>>>(src, dst, x, x16, bout, out, E, N * 16, out_size, EB);

    const int GB = (N + 63) / 64;          // gemm blocks
    const int HB = (N + 7) / 8;            // hop blocks (warp per node)
    const int FULL = GB + HB;

    // ---- layer 0 ----
    k_stage<0, true ><<<FULL, 256>>>(x16, W0,         accp, b0, nullptr, hA, nullptr, nullptr, nullptr, nullptr, N, GB);
    k_stage<1, true ><<<FULL, 256>>>(hA,  W0 + 4096,  accp, nullptr, nullptr, hB, nullptr, nullptr, nullptr, nullptr, N, GB);
    k_stage<1, true ><<<FULL, 256>>>(hB,  W0 + 8192,  accp, nullptr, nullptr, hA, nullptr, nullptr, nullptr, nullptr, N, GB);
    k_stage<2, false><<<GB,   256>>>(hA,  W0 + 12288, accp, nullptr, al0, nullptr, y16, nullptr, nullptr, nullptr, N, GB);

    // ---- layer 1 ----
    k_stage<0, true ><<<FULL, 256>>>(y16, W1,         accp, b1, nullptr, hB, nullptr, nullptr, nullptr, nullptr, N, GB);
    k_stage<1, true ><<<FULL, 256>>>(hB,  W1 + 4096,  accp, nullptr, nullptr, hA, nullptr, nullptr, nullptr, nullptr, N, GB);
    k_stage<1, true ><<<FULL, 256>>>(hA,  W1 + 8192,  accp, nullptr, nullptr, hB, nullptr, nullptr, nullptr, nullptr, N, GB);
    k_stage<3, false><<<GB,   256>>>(hB,  W1 + 12288, accp, nullptr, al1, nullptr, nullptr, bids, Wout, out, N, GB);
}

// round 5
// speedup vs baseline: 1.1579x; 1.0383x over previous
#include <cuda_runtime.h>
#include <cuda_fp16.h>

#define D 64
#define NMAX 50048
#define EMAX 800000

typedef unsigned long long ull;

// ---------------- scratch (no allocation allowed) ----------------
__device__ int    g_degi[NMAX];
__device__ int    g_cursor[NMAX];
__device__ float  g_dinv[NMAX];
__device__ int    g_rowptr[NMAX + 1];
__device__ ull    g_state[64];           // lookback scan state (value<<2 | status)
__device__ int2   g_edge[EMAX + 4];      // {src, wn bits}; padded for int4 tail
__device__ __half g_x16[(size_t)NMAX * D];
__device__ __half g_hA16[(size_t)NMAX * D];
__device__ __half g_hB16[(size_t)NMAX * D];
__device__ __half g_y16[(size_t)NMAX * D];
__device__ float  g_acc[(size_t)NMAX * D];

// ---------------- degree count (also resets scan state) ----------------
__global__ void k_deg(const int* __restrict__ dst, int E) {
    int e = blockIdx.x * blockDim.x + threadIdx.x;
    if (blockIdx.x == 0 && threadIdx.x < 64) g_state[threadIdx.x] = 0ull;
    if (e < E) atomicAdd(&g_degi[dst[e]], 1);
}

// ---------------- single-pass decoupled-lookback scan + dinv + cursor ----
__global__ void __launch_bounds__(1024) k_scan(int n) {
    const int tid = threadIdx.x;
    const int lane = tid & 31;
    const int w = tid >> 5;
    const int i = blockIdx.x * 1024 + tid;
    int v = (i < n) ? g_degi[i] : 0;

    int s = v;
#pragma unroll
    for (int off = 1; off < 32; off <<= 1) {
        int t = __shfl_up_sync(0xffffffffu, s, off);
        if (lane >= off) s += t;
    }
    __shared__ int wsum[32];
    if (lane == 31) wsum[w] = s;
    __syncthreads();
    if (w == 0) {
        int t = wsum[lane];
#pragma unroll
        for (int off = 1; off < 32; off <<= 1) {
            int u = __shfl_up_sync(0xffffffffu, t, off);
            if (lane >= off) t += u;
        }
        wsum[lane] = t;
    }
    __syncthreads();
    const int incl = s + (w > 0 ? wsum[w - 1] : 0);
    const int total = wsum[31];

    __shared__ int base_sh;
    if (tid == 0) {
        if (blockIdx.x == 0) {
            atomicExch(&g_state[0], ((ull)(unsigned)total << 2) | 2ull);
            base_sh = 0;
        } else {
            atomicExch(&g_state[blockIdx.x], ((ull)(unsigned)total << 2) | 1ull);
            int base = 0;
            for (int b = blockIdx.x - 1; b >= 0; b--) {
                ull st;
                do { st = atomicAdd(&g_state[b], 0ull); } while ((st & 3ull) == 0ull);
                base += (int)(unsigned)(st >> 2);
                if ((st & 3ull) == 2ull) break;
            }
            atomicExch(&g_state[blockIdx.x], ((ull)(unsigned)(base + total) << 2) | 2ull);
            base_sh = base;
        }
    }
    __syncthreads();
    const int base = base_sh;

    if (i < n) {
        int di = g_degi[i];
        int inclusive = base + incl;
        int excl = inclusive - di;
        g_rowptr[i] = excl;
        g_cursor[i] = excl;
        g_dinv[i] = (di > 0) ? rsqrtf((float)di) : 0.0f;
        if (i == n - 1) g_rowptr[n] = inclusive;
    }
}

// ---------------- fill CSR + quantize x + init out (block-range split) ----
__global__ void k_fillquant(const int* __restrict__ src, const int* __restrict__ dst,
                            const float* __restrict__ x, __half* __restrict__ x16,
                            const float* __restrict__ bout, float* __restrict__ out,
                            int E, int n4, int G, int EB) {
    if ((int)blockIdx.x < EB) {
        int e = blockIdx.x * 256 + threadIdx.x;
        if (e >= E) return;
        int s = src[e], d = dst[e];
        int pos = atomicAdd(&g_cursor[d], 1);
        int2 ed;
        ed.x = s;
        ed.y = __float_as_int(g_dinv[s] * g_dinv[d]);
        g_edge[pos] = ed;
    } else if ((int)blockIdx.x == gridDim.x - 1) {
        int i = threadIdx.x;
        if (i < G) out[i] = bout[0];
    } else {
        int i = (blockIdx.x - EB) * 256 + threadIdx.x;
        if (i >= n4) return;
        float4 v = ((const float4*)x)[i];
        __half2 a = __floats2half2_rn(v.x, v.y);
        __half2 b = __floats2half2_rn(v.z, v.w);
        uint2 p;
        p.x = *(unsigned*)&a;
        p.y = *(unsigned*)&b;
        ((uint2*)x16)[i] = p;
    }
}

// ---------------- ldmatrix / mma helpers ----------------
#define LDSM_X4(r0, r1, r2, r3, a) \
    asm volatile("ldmatrix.sync.aligned.m8n8.x4.shared.b16 {%0,%1,%2,%3}, [%4];" \
                 : "=r"(r0), "=r"(r1), "=r"(r2), "=r"(r3) : "r"(a))
#define LDSM_X4_T(r0, r1, r2, r3, a) \
    asm volatile("ldmatrix.sync.aligned.m8n8.x4.trans.shared.b16 {%0,%1,%2,%3}, [%4];" \
                 : "=r"(r0), "=r"(r1), "=r"(r2), "=r"(r3) : "r"(a))
#define HMMA(d0, d1, d2, d3, a0, a1, a2, a3, b0, b1) \
    asm volatile("mma.sync.aligned.m16n8k16.row.col.f32.f16.f16.f32 " \
                 "{%0,%1,%2,%3}, {%4,%5,%6,%7}, {%8,%9}, {%0,%1,%2,%3};" \
                 : "+f"(d0), "+f"(d1), "+f"(d2), "+f"(d3) \
                 : "r"(a0), "r"(a1), "r"(a2), "r"(a3), "r"(b0), "r"(b1))

// smem tiles, stride 72 halfs (144B) -> conflict-free ldmatrix
#define HS_STRIDE 72

// ---------------- stage kernel: HMMA GEMM blocks + hop blocks ----------
// GMODE 0: acc = h@W + bias        GMODE 1: acc += h@W
// GMODE 2: y16 = prelu(acc + h@W)  GMODE 3: pool(prelu(acc + h@W)) -> out
template <int GMODE, bool HOP>
__global__ void __launch_bounds__(256) k_stage(const __half* __restrict__ hin,
                                               const float* __restrict__ W,
                                               float* __restrict__ acc,
                                               const float* __restrict__ bias,
                                               const float* __restrict__ alpha,
                                               __half* __restrict__ hopout,
                                               __half* __restrict__ y16,
                                               const int* __restrict__ bids,
                                               const float* __restrict__ Wout,
                                               float* __restrict__ out,
                                               int N, int GB) {
    __shared__ __half Hs[64 * HS_STRIDE];
    __shared__ __half Whi[64 * HS_STRIDE];
    __shared__ __half Wlo[64 * HS_STRIDE];

    const int tid = threadIdx.x;

    if (HOP && (int)blockIdx.x >= GB) {
        const int lane = tid & 31;
        const int node = (blockIdx.x - GB) * 8 + (tid >> 5);
        if (node >= N) return;
        int p = g_rowptr[node];
        const int end = g_rowptr[node + 1];
        float ax = 0.f, ay = 0.f;
        if (p < end && (p & 1)) {  // align to int4
            int2 e = g_edge[p];
            float wv = __int_as_float(e.y);
            float2 v = __half22float2(__ldg((const __half2*)&hin[(size_t)e.x * D + lane * 2]));
            ax += wv * v.x;  ay += wv * v.y;
            p++;
        }
        for (; p + 8 <= end; p += 8) {  // 8-edge unroll: MLP 8
            int4 a = *(const int4*)&g_edge[p];
            int4 b = *(const int4*)&g_edge[p + 2];
            int4 c = *(const int4*)&g_edge[p + 4];
            int4 dd = *(const int4*)&g_edge[p + 6];
            float2 v0 = __half22float2(__ldg((const __half2*)&hin[(size_t)a.x * D + lane * 2]));
            float2 v1 = __half22float2(__ldg((const __half2*)&hin[(size_t)a.z * D + lane * 2]));
            float2 v2 = __half22float2(__ldg((const __half2*)&hin[(size_t)b.x * D + lane * 2]));
            float2 v3 = __half22float2(__ldg((const __half2*)&hin[(size_t)b.z * D + lane * 2]));
            float2 v4 = __half22float2(__ldg((const __half2*)&hin[(size_t)c.x * D + lane * 2]));
            float2 v5 = __half22float2(__ldg((const __half2*)&hin[(size_t)c.z * D + lane * 2]));
            float2 v6 = __half22float2(__ldg((const __half2*)&hin[(size_t)dd.x * D + lane * 2]));
            float2 v7 = __half22float2(__ldg((const __half2*)&hin[(size_t)dd.z * D + lane * 2]));
            float w0 = __int_as_float(a.y),  w1 = __int_as_float(a.w);
            float w2 = __int_as_float(b.y),  w3 = __int_as_float(b.w);
            float w4 = __int_as_float(c.y),  w5 = __int_as_float(c.w);
            float w6 = __int_as_float(dd.y), w7 = __int_as_float(dd.w);
            ax += w0 * v0.x;  ay += w0 * v0.y;
            ax += w1 * v1.x;  ay += w1 * v1.y;
            ax += w2 * v2.x;  ay += w2 * v2.y;
            ax += w3 * v3.x;  ay += w3 * v3.y;
            ax += w4 * v4.x;  ay += w4 * v4.y;
            ax += w5 * v5.x;  ay += w5 * v5.y;
            ax += w6 * v6.x;  ay += w6 * v6.y;
            ax += w7 * v7.x;  ay += w7 * v7.y;
        }
        for (; p + 2 <= end; p += 2) {
            int4 a = *(const int4*)&g_edge[p];
            float w0 = __int_as_float(a.y), w1 = __int_as_float(a.w);
            float2 v0 = __half22float2(__ldg((const __half2*)&hin[(size_t)a.x * D + lane * 2]));
            float2 v1 = __half22float2(__ldg((const __half2*)&hin[(size_t)a.z * D + lane * 2]));
            ax += w0 * v0.x;  ay += w0 * v0.y;
            ax += w1 * v1.x;  ay += w1 * v1.y;
        }
        if (p < end) {
            int2 e = g_edge[p];
            float wv = __int_as_float(e.y);
            float2 v = __half22float2(__ldg((const __half2*)&hin[(size_t)e.x * D + lane * 2]));
            ax += wv * v.x;  ay += wv * v.y;
        }
        *(__half2*)&hopout[(size_t)node * D + lane * 2] = __floats2half2_rn(ax, ay);
        return;
    }

    // ================= HMMA GEMM block =================
    const int n0blk = blockIdx.x * 64;

    // stage Hs (fp16 rows of hin), 8 halfs per thread x2
#pragma unroll
    for (int i = 0; i < 2; i++) {
        int idx = tid + i * 256;            // 0..511 chunks of 8 halfs
        int r = idx >> 3;
        int c8 = (idx & 7) * 8;
        int4 v = make_int4(0, 0, 0, 0);
        if (n0blk + r < N) v = *(const int4*)&hin[(size_t)(n0blk + r) * D + c8];
        *(int4*)&Hs[r * HS_STRIDE + c8] = v;
    }
    // stage W split into hi/lo fp16 planes
#pragma unroll
    for (int i = 0; i < 4; i++) {
        int idx = tid + i * 256;            // 0..1023 chunks of 4 floats
        int r = idx >> 4;
        int c4 = (idx & 15) * 4;
        float4 wv = *(const float4*)&W[r * 64 + c4];
        __half hx = __float2half_rn(wv.x), hy = __float2half_rn(wv.y);
        __half hz = __float2half_rn(wv.z), hw = __float2half_rn(wv.w);
        __half lx = __float2half_rn(wv.x - __half2float(hx));
        __half ly = __float2half_rn(wv.y - __half2float(hy));
        __half lz = __float2half_rn(wv.z - __half2float(hz));
        __half lw = __float2half_rn(wv.w - __half2float(hw));
        __half2* ph = (__half2*)&Whi[r * HS_STRIDE + c4];
        __half2* pl = (__half2*)&Wlo[r * HS_STRIDE + c4];
        ph[0] = __halves2half2(hx, hy);  ph[1] = __halves2half2(hz, hw);
        pl[0] = __halves2half2(lx, ly);  pl[1] = __halves2half2(lz, lw);
    }
    __syncthreads();

    const int w = tid >> 5;
    const int lane = tid & 31;
    const int m0 = (w & 3) * 16;            // warp m-tile
    const int n0w = (w >> 2) * 32;          // warp n-tile
    const int lr = lane & 15;
    const int lc = (lane >> 4) * 8;

    float d0[4], d1[4], d2[4], d3[4];       // 4 n8-tiles x 4 f32
#pragma unroll
    for (int j = 0; j < 4; j++) { d0[j] = d1[j] = d2[j] = d3[j] = 0.f; }

    unsigned aAddr = (unsigned)__cvta_generic_to_shared(&Hs[(m0 + lr) * HS_STRIDE + lc]);
    unsigned bhAddr0 = (unsigned)__cvta_generic_to_shared(&Whi[lr * HS_STRIDE + n0w + lc]);
    unsigned bhAddr1 = (unsigned)__cvta_generic_to_shared(&Whi[lr * HS_STRIDE + n0w + 16 + lc]);
    unsigned blAddr0 = (unsigned)__cvta_generic_to_shared(&Wlo[lr * HS_STRIDE + n0w + lc]);
    unsigned blAddr1 = (unsigned)__cvta_generic_to_shared(&Wlo[lr * HS_STRIDE + n0w + 16 + lc]);
    const unsigned kstepB = 16 * HS_STRIDE * 2;  // bytes per 16 k-rows

#pragma unroll
    for (int ks = 0; ks < 4; ks++) {
        unsigned a0, a1, a2, a3;
        LDSM_X4(a0, a1, a2, a3, aAddr + ks * 32);          // +16 halfs per kstep
        unsigned h0, h1, h2, h3, h4, h5, h6, h7;
        LDSM_X4_T(h0, h1, h2, h3, bhAddr0 + ks * kstepB);  // n-tiles 0,1 (hi)
        LDSM_X4_T(h4, h5, h6, h7, bhAddr1 + ks * kstepB);  // n-tiles 2,3 (hi)
        unsigned l0, l1, l2, l3, l4, l5, l6, l7;
        LDSM_X4_T(l0, l1, l2, l3, blAddr0 + ks * kstepB);
        LDSM_X4_T(l4, l5, l6, l7, blAddr1 + ks * kstepB);
        HMMA(d0[0], d1[0], d2[0], d3[0], a0, a1, a2, a3, h0, h1);
        HMMA(d0[1], d1[1], d2[1], d3[1], a0, a1, a2, a3, h2, h3);
        HMMA(d0[2], d1[2], d2[2], d3[2], a0, a1, a2, a3, h4, h5);
        HMMA(d0[3], d1[3], d2[3], d3[3], a0, a1, a2, a3, h6, h7);
        HMMA(d0[0], d1[0], d2[0], d3[0], a0, a1, a2, a3, l0, l1);
        HMMA(d0[1], d1[1], d2[1], d3[1], a0, a1, a2, a3, l2, l3);
        HMMA(d0[2], d1[2], d2[2], d3[2], a0, a1, a2, a3, l4, l5);
        HMMA(d0[3], d1[3], d2[3], d3[3], a0, a1, a2, a3, l6, l7);
    }

    // ---- epilogue ----
    const int grp = lane >> 2;
    const int qt = lane & 3;
    const int row0 = n0blk + m0 + grp;
    const int row1 = row0 + 8;
    float a0s = 0.f;
    if (GMODE >= 2) a0s = alpha[0];
    float part0 = 0.f, part1 = 0.f;

#pragma unroll
    for (int j = 0; j < 4; j++) {
        const int cb = n0w + j * 8 + qt * 2;
        float2 bvj = make_float2(0.f, 0.f);
        if (GMODE == 0) bvj = *(const float2*)&bias[cb];
        float2 wvj = make_float2(0.f, 0.f);
        if (GMODE == 3) wvj = *(const float2*)&Wout[cb];

        if (GMODE == 0) {
            if (row0 < N) {
                float2 o = make_float2(d0[j] + bvj.x, d1[j] + bvj.y);
                *(float2*)&acc[(size_t)row0 * D + cb] = o;
            }
            if (row1 < N) {
                float2 o = make_float2(d2[j] + bvj.x, d3[j] + bvj.y);
                *(float2*)&acc[(size_t)row1 * D + cb] = o;
            }
        } else if (GMODE == 1) {
            if (row0 < N) {
                float* ap = &acc[(size_t)row0 * D + cb];
                float2 o = *(const float2*)ap;
                o.x += d0[j]; o.y += d1[j];
                *(float2*)ap = o;
            }
            if (row1 < N) {
                float* ap = &acc[(size_t)row1 * D + cb];
                float2 o = *(const float2*)ap;
                o.x += d2[j]; o.y += d3[j];
                *(float2*)ap = o;
            }
        } else {
            if (row0 < N) {
                float2 o = *(const float2*)&acc[(size_t)row0 * D + cb];
                o.x += d0[j]; o.y += d1[j];
                o.x = (o.x >= 0.f) ? o.x : a0s * o.x;
                o.y = (o.y >= 0.f) ? o.y : a0s * o.y;
                if (GMODE == 2) {
                    *(__half2*)&y16[(size_t)row0 * D + cb] = __floats2half2_rn(o.x, o.y);
                } else {
                    part0 += o.x * wvj.x + o.y * wvj.y;
                }
            }
            if (row1 < N) {
                float2 o = *(const float2*)&acc[(size_t)row1 * D + cb];
                o.x += d2[j]; o.y += d3[j];
                o.x = (o.x >= 0.f) ? o.x : a0s * o.x;
                o.y = (o.y >= 0.f) ? o.y : a0s * o.y;
                if (GMODE == 2) {
                    *(__half2*)&y16[(size_t)row1 * D + cb] = __floats2half2_rn(o.x, o.y);
                } else {
                    part1 += o.x * wvj.x + o.y * wvj.y;
                }
            }
        }
    }

    if (GMODE == 3) {
        // reduce across the 4 quad lanes (same grp)
        part0 += __shfl_xor_sync(0xffffffffu, part0, 1);
        part0 += __shfl_xor_sync(0xffffffffu, part0, 2);
        part1 += __shfl_xor_sync(0xffffffffu, part1, 1);
        part1 += __shfl_xor_sync(0xffffffffu, part1, 2);
        if (qt == 0) {
            if (row0 < N) atomicAdd(&out[bids[row0]], part0);
            if (row1 < N) atomicAdd(&out[bids[row1]], part1);
        }
    }
}

// ---------------- launch ----------------
extern "C" void kernel_launch(void* const* d_in, const int* in_sizes, int n_in,
                              void* d_out, int out_size) {
    const float* x    = (const float*)d_in[0];
    const int*   ei   = (const int*)d_in[1];
    const int*   bids = (const int*)d_in[2];
    const float* W0   = (const float*)d_in[3];
    const float* b0   = (const float*)d_in[4];
    const float* W1   = (const float*)d_in[5];
    const float* b1   = (const float*)d_in[6];
    const float* al0  = (const float*)d_in[7];
    const float* al1  = (const float*)d_in[8];
    const float* Wout = (const float*)d_in[9];
    const float* bout = (const float*)d_in[10];
    float* out = (float*)d_out;

    const int N = in_sizes[0] / D;
    const int E = in_sizes[1] / 2;
    const int* src = ei;
    const int* dst = ei + E;

    void* p_degi;
    __half *x16, *hA, *hB, *y16;
    float* accp;
    cudaGetSymbolAddress(&p_degi, g_degi);
    cudaGetSymbolAddress((void**)&x16, g_x16);
    cudaGetSymbolAddress((void**)&hA, g_hA16);
    cudaGetSymbolAddress((void**)&hB, g_hB16);
    cudaGetSymbolAddress((void**)&y16, g_y16);
    cudaGetSymbolAddress((void**)&accp, g_acc);

    cudaMemsetAsync(p_degi, 0, (size_t)N * sizeof(int));

    const int EB = (E + 255) / 256;
    const int QB = (N * 16 + 255) / 256;
    k_deg<<<EB, 256>>>(dst, E);
    k_scan<<<(N + 1023) / 1024, 1024>>>(N);
    k_fillquant<<<EB + QB + 1, 256>>>(src, dst, x, x16, bout, out, E, N * 16, out_size, EB);

    const int GB = (N + 63) / 64;          // gemm blocks
    const int HB = (N + 7) / 8;            // hop blocks (warp per node)
    const int FULL = GB + HB;

    // ---- layer 0 ----
    k_stage<0, true ><<<FULL, 256>>>(x16, W0,         accp, b0, nullptr, hA, nullptr, nullptr, nullptr, nullptr, N, GB);
    k_stage<1, true ><<<FULL, 256>>>(hA,  W0 + 4096,  accp, nullptr, nullptr, hB, nullptr, nullptr, nullptr, nullptr, N, GB);
    k_stage<1, true ><<<FULL, 256>>>(hB,  W0 + 8192,  accp, nullptr, nullptr, hA, nullptr, nullptr, nullptr, nullptr, N, GB);
    k_stage<2, false><<<GB,   256>>>(hA,  W0 + 12288, accp, nullptr, al0, nullptr, y16, nullptr, nullptr, nullptr, N, GB);

    // ---- layer 1 ----
    k_stage<0, true ><<<FULL, 256>>>(y16, W1,         accp, b1, nullptr, hB, nullptr, nullptr, nullptr, nullptr, N, GB);
    k_stage<1, true ><<<FULL, 256>>>(hB,  W1 + 4096,  accp, nullptr, nullptr, hA, nullptr, nullptr, nullptr, nullptr, N, GB);
    k_stage<1, true ><<<FULL, 256>>>(hA,  W1 + 8192,  accp, nullptr, nullptr, hB, nullptr, nullptr, nullptr, nullptr, N, GB);
    k_stage<3, false><<<GB,   256>>>(hB,  W1 + 12288, accp, nullptr, al1, nullptr, nullptr, bids, Wout, out, N, GB);
}